// round 16
// baseline (speedup 1.0000x reference)
#include <cuda_runtime.h>

#define MAXN 100000
#define EPS_F 1e-8f
#define EPS_D 1e-8

// Scratch (allocation-free rule: __device__ globals)
__device__ float4 g_nodes[MAXN];          // pos.xyz, phi  (1.6 MB, L2-resident)
__device__ float  g_acc[MAXN * 12];       // per node: b0,b1,b2,a00 | a01,a02,a11,a12 | a22,pad,pad,pad

__device__ __forceinline__ void red_add_v4(float* addr, float a, float b, float c, float d) {
    asm volatile("red.global.add.v4.f32 [%0], {%1, %2, %3, %4};"
                 :: "l"(addr), "f"(a), "f"(b), "f"(c), "f"(d) : "memory");
}
__device__ __forceinline__ void red_add_f32(float* addr, float a) {
    asm volatile("red.global.add.f32 [%0], %1;" :: "l"(addr), "f"(a) : "memory");
}

__global__ void pack_kernel(const float* __restrict__ pos,
                            const float* __restrict__ phi, int n) {
    int i = blockIdx.x * blockDim.x + threadIdx.x;
    if (i >= n) return;
    g_nodes[i] = make_float4(pos[3 * i], pos[3 * i + 1], pos[3 * i + 2], phi[i]);
}

struct EdgeVals {
    float b0, b1, b2, a00, a01, a02, a11, a12, a22;
};

__device__ __forceinline__ EdgeVals edge_compute(float4 nu, float4 nv) {
    float dx = nv.x - nu.x, dy = nv.y - nu.y, dz = nv.z - nu.z;
    float dphi = nv.w - nu.w;
    float s = dx * dx + dy * dy + dz * dz;
    float t = sqrtf(s) + EPS_F;
    float w = 1.0f / (t * t);
    float wd = w * dphi;
    EdgeVals e;
    e.b0 = wd * dx;     e.b1 = wd * dy;     e.b2 = wd * dz;
    e.a00 = w * dx * dx; e.a01 = w * dx * dy; e.a02 = w * dx * dz;
    e.a11 = w * dy * dy; e.a12 = w * dy * dz; e.a22 = w * dz * dz;
    return e;
}

__device__ __forceinline__ void edge_scatter(int u, int v, const EdgeVals& e) {
    float* pu = g_acc + 12 * u;
    float* pv = g_acc + 12 * v;
    red_add_v4(pu,     e.b0,  e.b1,  e.b2,  e.a00);
    red_add_v4(pv,     e.b0,  e.b1,  e.b2,  e.a00);
    red_add_v4(pu + 4, e.a01, e.a02, e.a11, e.a12);
    red_add_v4(pv + 4, e.a01, e.a02, e.a11, e.a12);
    red_add_f32(pu + 8, e.a22);
    red_add_f32(pv + 8, e.a22);
}

// Process only the first half of the symmetrized edge list; each undirected
// edge contributes IDENTICAL (A, b) increments to both endpoints:
//   outer(dx,dx) invariant under dx -> -dx;  (dphi*dx) invariant under joint negation.
// 2 edges per thread: front-batch all 4 gathers (MLP), then compute, then
// issue all 12 reds back-to-back (REDG issue stream is the bottleneck).
__global__ void __launch_bounds__(256) edge_kernel(const int* __restrict__ rows,
                                                   const int* __restrict__ cols, int ehalf) {
    int i0 = (blockIdx.x * blockDim.x + threadIdx.x) * 2;
    int i1 = i0 + 1;
    if (i0 >= ehalf) return;
    bool has1 = (i1 < ehalf);

    int u0 = rows[i0], v0 = cols[i0];
    int u1 = has1 ? rows[i1] : u0;
    int v1 = has1 ? cols[i1] : v0;

    // Front-batched gathers (independent, overlap in L1tex queue)
    float4 nu0 = __ldg(&g_nodes[u0]);
    float4 nv0 = __ldg(&g_nodes[v0]);
    float4 nu1 = __ldg(&g_nodes[u1]);
    float4 nv1 = __ldg(&g_nodes[v1]);

    EdgeVals e0 = edge_compute(nu0, nv0);
    edge_scatter(u0, v0, e0);
    if (has1) {
        EdgeVals e1 = edge_compute(nu1, nv1);
        edge_scatter(u1, v1, e1);
    }
}

// (A + eps*I) x = b, A symmetric 3x3, solved via adjugate in double.
__global__ void solve_kernel(float* __restrict__ out, int n) {
    int i = blockIdx.x * blockDim.x + threadIdx.x;
    if (i >= n) return;
    const float4* ap = reinterpret_cast<const float4*>(g_acc + 12 * i);
    float4 q0 = ap[0];   // b0,b1,b2,a00
    float4 q1 = ap[1];   // a01,a02,a11,a12
    float  a22 = g_acc[12 * i + 8];

    double b0 = q0.x, b1 = q0.y, b2 = q0.z;
    double m00 = (double)q0.w + EPS_D;
    double m01 = q1.x, m02 = q1.y;
    double m11 = (double)q1.z + EPS_D;
    double m12 = q1.w;
    double m22 = (double)a22 + EPS_D;

    double c00 = m11 * m22 - m12 * m12;
    double c01 = m02 * m12 - m01 * m22;
    double c02 = m01 * m12 - m02 * m11;
    double c11 = m00 * m22 - m02 * m02;
    double c12 = m01 * m02 - m00 * m12;
    double c22 = m00 * m11 - m01 * m01;
    double det = m00 * c00 + m01 * c01 + m02 * c02;
    double inv = 1.0 / det;

    double x0 = (c00 * b0 + c01 * b1 + c02 * b2) * inv;
    double x1 = (c01 * b0 + c11 * b1 + c12 * b2) * inv;
    double x2 = (c02 * b0 + c12 * b1 + c22 * b2) * inv;

    out[3 * i]     = (float)x0;
    out[3 * i + 1] = (float)x1;
    out[3 * i + 2] = (float)x2;
}

extern "C" void kernel_launch(void* const* d_in, const int* in_sizes, int n_in,
                              void* d_out, int out_size) {
    const float* pos = (const float*)d_in[0];
    const float* phi = (const float*)d_in[1];
    const int*   ei  = (const int*)d_in[2];
    float* out = (float*)d_out;

    int  n      = in_sizes[1];            // N nodes (phi element count)
    long etotal = (long)in_sizes[2] / 2;  // undirected (symmetrized) edge count
    int  ehalf  = (int)(etotal / 2);      // unique edges before symmetrization

    // Zero accumulators via a memset graph node (cheaper than scattered stores)
    void* accptr = nullptr;
    cudaGetSymbolAddress(&accptr, g_acc);
    cudaMemsetAsync(accptr, 0, (size_t)n * 12 * sizeof(float), 0);

    const int TB = 256;
    pack_kernel<<<(n + TB - 1) / TB, TB>>>(pos, phi, n);
    int nthreads = (ehalf + 1) / 2;
    edge_kernel<<<(nthreads + TB - 1) / TB, TB>>>(ei, ei + etotal, ehalf);
    solve_kernel<<<(n + TB - 1) / TB, TB>>>(out, n);
}

// round 17
// speedup vs baseline: 1.0035x; 1.0035x over previous
#include <cuda_runtime.h>

#define MAXN 100000
#define EPS_F 1e-8f
#define EPS_D 1e-8

// Scratch (allocation-free rule: __device__ globals)
__device__ float4 g_nodes[MAXN];          // pos.xyz, phi  (1.6 MB, L2-resident)
__device__ float  g_acc[MAXN * 12];       // per node: b0,b1,b2,a00 | a01,a02,a11,a12 | a22,pad,pad,pad

__device__ __forceinline__ void red_add_v4(float* addr, float a, float b, float c, float d) {
    asm volatile("red.global.add.v4.f32 [%0], {%1, %2, %3, %4};"
                 :: "l"(addr), "f"(a), "f"(b), "f"(c), "f"(d) : "memory");
}
__device__ __forceinline__ void red_add_f32(float* addr, float a) {
    asm volatile("red.global.add.f32 [%0], %1;" :: "l"(addr), "f"(a) : "memory");
}

__global__ void pack_kernel(const float* __restrict__ pos,
                            const float* __restrict__ phi, int n) {
    int i = blockIdx.x * blockDim.x + threadIdx.x;
    if (i >= n) return;
    g_nodes[i] = make_float4(pos[3 * i], pos[3 * i + 1], pos[3 * i + 2], phi[i]);
}

struct EdgeVals {
    float b0, b1, b2, a00, a01, a02, a11, a12, a22;
};

__device__ __forceinline__ EdgeVals edge_compute(float4 nu, float4 nv) {
    float dx = nv.x - nu.x, dy = nv.y - nu.y, dz = nv.z - nu.z;
    float dphi = nv.w - nu.w;
    float s = dx * dx + dy * dy + dz * dz;
    float t = sqrtf(s) + EPS_F;
    float w = 1.0f / (t * t);
    float wd = w * dphi;
    EdgeVals e;
    e.b0 = wd * dx;     e.b1 = wd * dy;     e.b2 = wd * dz;
    e.a00 = w * dx * dx; e.a01 = w * dx * dy; e.a02 = w * dx * dz;
    e.a11 = w * dy * dy; e.a12 = w * dy * dz; e.a22 = w * dz * dz;
    return e;
}

__device__ __forceinline__ void edge_scatter(int u, int v, const EdgeVals& e) {
    float* pu = g_acc + 12 * u;
    float* pv = g_acc + 12 * v;
    red_add_v4(pu,     e.b0,  e.b1,  e.b2,  e.a00);
    red_add_v4(pv,     e.b0,  e.b1,  e.b2,  e.a00);
    red_add_v4(pu + 4, e.a01, e.a02, e.a11, e.a12);
    red_add_v4(pv + 4, e.a01, e.a02, e.a11, e.a12);
    red_add_f32(pu + 8, e.a22);
    red_add_f32(pv + 8, e.a22);
}

// Process only the first half of the symmetrized edge list; each undirected
// edge contributes IDENTICAL (A, b) increments to both endpoints:
//   outer(dx,dx) invariant under dx -> -dx;  (dphi*dx) invariant under joint negation.
// 2 edges per thread: front-batch all 4 gathers (MLP), then compute, then
// issue all 12 reds back-to-back (REDG issue stream is the bottleneck).
__global__ void __launch_bounds__(256) edge_kernel(const int* __restrict__ rows,
                                                   const int* __restrict__ cols, int ehalf) {
    int i0 = (blockIdx.x * blockDim.x + threadIdx.x) * 2;
    int i1 = i0 + 1;
    if (i0 >= ehalf) return;
    bool has1 = (i1 < ehalf);

    int u0 = rows[i0], v0 = cols[i0];
    int u1 = has1 ? rows[i1] : u0;
    int v1 = has1 ? cols[i1] : v0;

    // Front-batched gathers (independent, overlap in L1tex queue)
    float4 nu0 = __ldg(&g_nodes[u0]);
    float4 nv0 = __ldg(&g_nodes[v0]);
    float4 nu1 = __ldg(&g_nodes[u1]);
    float4 nv1 = __ldg(&g_nodes[v1]);

    EdgeVals e0 = edge_compute(nu0, nv0);
    edge_scatter(u0, v0, e0);
    if (has1) {
        EdgeVals e1 = edge_compute(nu1, nv1);
        edge_scatter(u1, v1, e1);
    }
}

// (A + eps*I) x = b, A symmetric 3x3, solved via adjugate in double.
__global__ void solve_kernel(float* __restrict__ out, int n) {
    int i = blockIdx.x * blockDim.x + threadIdx.x;
    if (i >= n) return;
    const float4* ap = reinterpret_cast<const float4*>(g_acc + 12 * i);
    float4 q0 = ap[0];   // b0,b1,b2,a00
    float4 q1 = ap[1];   // a01,a02,a11,a12
    float  a22 = g_acc[12 * i + 8];

    double b0 = q0.x, b1 = q0.y, b2 = q0.z;
    double m00 = (double)q0.w + EPS_D;
    double m01 = q1.x, m02 = q1.y;
    double m11 = (double)q1.z + EPS_D;
    double m12 = q1.w;
    double m22 = (double)a22 + EPS_D;

    double c00 = m11 * m22 - m12 * m12;
    double c01 = m02 * m12 - m01 * m22;
    double c02 = m01 * m12 - m02 * m11;
    double c11 = m00 * m22 - m02 * m02;
    double c12 = m01 * m02 - m00 * m12;
    double c22 = m00 * m11 - m01 * m01;
    double det = m00 * c00 + m01 * c01 + m02 * c02;
    double inv = 1.0 / det;

    double x0 = (c00 * b0 + c01 * b1 + c02 * b2) * inv;
    double x1 = (c01 * b0 + c11 * b1 + c12 * b2) * inv;
    double x2 = (c02 * b0 + c12 * b1 + c22 * b2) * inv;

    out[3 * i]     = (float)x0;
    out[3 * i + 1] = (float)x1;
    out[3 * i + 2] = (float)x2;
}

extern "C" void kernel_launch(void* const* d_in, const int* in_sizes, int n_in,
                              void* d_out, int out_size) {
    const float* pos = (const float*)d_in[0];
    const float* phi = (const float*)d_in[1];
    const int*   ei  = (const int*)d_in[2];
    float* out = (float*)d_out;

    int  n      = in_sizes[1];            // N nodes (phi element count)
    long etotal = (long)in_sizes[2] / 2;  // undirected (symmetrized) edge count
    int  ehalf  = (int)(etotal / 2);      // unique edges before symmetrization

    // Zero accumulators via a memset graph node (cheaper than scattered stores)
    void* accptr = nullptr;
    cudaGetSymbolAddress(&accptr, g_acc);
    cudaMemsetAsync(accptr, 0, (size_t)n * 12 * sizeof(float), 0);

    const int TB = 256;
    pack_kernel<<<(n + TB - 1) / TB, TB>>>(pos, phi, n);
    int nthreads = (ehalf + 1) / 2;
    edge_kernel<<<(nthreads + TB - 1) / TB, TB>>>(ei, ei + etotal, ehalf);
    solve_kernel<<<(n + TB - 1) / TB, TB>>>(out, n);
}